// round 15
// baseline (speedup 1.0000x reference)
#include <cuda_runtime.h>

#define FULL 0xFFFFFFFFu

// feat[b][n] scratch + per-batch completion counters (128B apart -> 64
// distinct L2 lines). __device__ globals = allowed scratch; zero at load,
// each batch's winner resets its counter for the next graph replay.
__device__ float g_feat[64 * 1024];
__device__ unsigned int g_cnt[64 * 32];

// Release-ordered ticket: publishes prior global stores (write-through to L2)
// WITHOUT __threadfence's CCTL.IVALL L1 flush that poisoned R13/R14.
__device__ __forceinline__ unsigned ticket_acq_rel(unsigned int* addr) {
    unsigned old;
    asm volatile("atom.acq_rel.gpu.global.add.u32 %0, [%1], %2;"
                 : "=r"(old) : "l"(addr), "r"(1u) : "memory");
    return old;
}

// 6 blocks/SM min -> ptxas caps regs at ~42 -> 48 warps/SM (75% occ).
__global__ __launch_bounds__(256, 6) void conv_chain_kernel(
    const float* __restrict__ x,
    const float* __restrict__ w1, const float* __restrict__ b1,
    const float* __restrict__ w2, const float* __restrict__ b2,
    const float* __restrict__ w3, const float* __restrict__ b3,
    const float* __restrict__ cw, const float* __restrict__ cb,
    float* __restrict__ out)
{
    // 8 warps per block, one row (b,n) per warp.
    __shared__ float sm[8][152];   // conv1 output for the 150->30 pool gather
    __shared__ int   sLast;

    const int tid  = threadIdx.x;
    const int warp = tid >> 5;
    const int lane = tid & 31;
    const int row  = blockIdx.x * 8 + warp;   // row in [0, 65536)

    const float4* X4 = reinterpret_cast<const float4*>(x + (size_t)row * 1200);
    float* S = sm[warp];

    // ---- conv1: K=10, stride=8, pad=1, out length 150, relu.
    // Output j = 32*it + lane, window x[8j-1 .. 8j+8]. Depth-2 pipeline:
    // only 4 float4s live at a time (low regs -> high occupancy).
    float4 a0, a1;
    {
        int jj = lane;                        // it=0: j = lane < 150 always
        a0 = X4[2 * jj];
        a1 = X4[2 * jj + 1];
    }

    float W1[10];
    #pragma unroll
    for (int k = 0; k < 10; k++) W1[k] = __ldg(&w1[k]);
    const float B1 = __ldg(b1);

    float carry = 0.0f;                       // x[8j-1] carry (x[-1] = pad)
    #pragma unroll
    for (int it = 0; it < 5; it++) {
        // prefetch next iteration's window
        float4 n0, n1;
        if (it < 4) {
            int j  = (it + 1) * 32 + lane;
            int jj = j < 150 ? j : 149;       // clamp (it==4 lanes 22..31 idle)
            n0 = X4[2 * jj];
            n1 = X4[2 * jj + 1];
        }

        // x[8j-1] = previous lane's a1.w
        float xm1 = __shfl_up_sync(FULL, a1.w, 1);
        if (lane == 0) xm1 = carry;
        carry = __shfl_sync(FULL, a1.w, 31);

        // x[8j+8] = next lane's a0.x; lane 31 takes next iter's lane-0 a0.x
        float nxt = (it < 4) ? __shfl_sync(FULL, n0.x, 0) : 0.0f;
        float a2  = __shfl_down_sync(FULL, a0.x, 1);
        if (lane == 31) a2 = nxt;
        int j = it * 32 + lane;
        if (j == 149) a2 = 0.0f;              // right pad

        float v = B1;
        v = fmaf(W1[0], xm1,  v);
        v = fmaf(W1[1], a0.x, v);
        v = fmaf(W1[2], a0.y, v);
        v = fmaf(W1[3], a0.z, v);
        v = fmaf(W1[4], a0.w, v);
        v = fmaf(W1[5], a1.x, v);
        v = fmaf(W1[6], a1.y, v);
        v = fmaf(W1[7], a1.z, v);
        v = fmaf(W1[8], a1.w, v);
        v = fmaf(W1[9], a2,   v);
        if (j < 150) S[j] = fmaxf(v, 0.0f);   // write y1 straight to smem

        a0 = n0; a1 = n1;
    }
    __syncwarp();

    // ---- maxpool k=5 s=5 (150 -> 30); relu no-op (inputs >= 0)
    float p = 0.0f;
    if (lane < 30) {
        p = S[5 * lane];
        #pragma unroll
        for (int k = 1; k < 5; k++) p = fmaxf(p, S[5 * lane + k]);
    }

    // ---- conv2: K=3 s=3 (30 -> 10), relu  (lanes 0..9 produce q)
    const float w20 = __ldg(&w2[0]), w21 = __ldg(&w2[1]), w22 = __ldg(&w2[2]);
    const float B2  = __ldg(b2);
    float pa = __shfl_sync(FULL, p, (3 * lane)     & 31);
    float pb = __shfl_sync(FULL, p, (3 * lane + 1) & 31);
    float pc = __shfl_sync(FULL, p, (3 * lane + 2) & 31);
    float q = fmaxf(fmaf(w20, pa, fmaf(w21, pb, fmaf(w22, pc, B2))), 0.0f);

    // ---- maxpool k=3 s=3 pad=1 (10 -> 4); relu no-op  (lanes 0..3)
    float qm = __shfl_sync(FULL, q, (3 * lane - 1) & 31);
    float q0 = __shfl_sync(FULL, q, (3 * lane)     & 31);
    float qp = __shfl_sync(FULL, q, (3 * lane + 1) & 31);
    float r;
    if (lane == 0)      r = fmaxf(q0, qp);        // window {-1(pad),0,1}
    else if (lane == 3) r = fmaxf(qm, q0);        // window {8,9,10(pad)}
    else                r = fmaxf(fmaxf(qm, q0), qp);

    // ---- conv3: K=4 s=1 (4 -> 1), relu -> feat
    float r0 = __shfl_sync(FULL, r, 0);
    float r1 = __shfl_sync(FULL, r, 1);
    float r2 = __shfl_sync(FULL, r, 2);
    float r3 = __shfl_sync(FULL, r, 3);
    if (lane == 0) {
        float f = __ldg(b3);
        f = fmaf(__ldg(&w3[0]), r0, f);
        f = fmaf(__ldg(&w3[1]), r1, f);
        f = fmaf(__ldg(&w3[2]), r2, f);
        f = fmaf(__ldg(&w3[3]), r3, f);
        g_feat[row] = fmaxf(f, 0.0f);
    }

    // ---- per-batch ticket with RELEASE atomic (no L1 flush). Stores are
    //      write-through; release ordering on the atomic publishes them.
    const int b = blockIdx.x >> 7;            // 128 blocks per batch
    __syncthreads();                          // all 8 feat stores issued
    if (tid == 0) {
        unsigned old = ticket_acq_rel(&g_cnt[b * 32]);
        sLast = (old == 127u) ? 1 : 0;
    }
    __syncthreads();
    if (!sLast) return;

    // ================= last block of batch b: compute its head =============
    // Acquire side of the winning atomic orders these reads; __ldcg reads at
    // L2 (the point of coherence for the write-through feat stores).
    const float4* f4 = reinterpret_cast<const float4*>(g_feat + b * 1024);
    const float4* c0 = reinterpret_cast<const float4*>(cw);
    const float4* c1 = reinterpret_cast<const float4*>(cw + 1024);
    const float4* c2 = reinterpret_cast<const float4*>(cw + 2048);

    float4 fv = __ldcg(&f4[tid]);             // 256 threads x 4 nodes
    float4 u0 = __ldg(&c0[tid]);
    float4 u1 = __ldg(&c1[tid]);
    float4 u2 = __ldg(&c2[tid]);

    float a0s = fv.x*u0.x + fv.y*u0.y + fv.z*u0.z + fv.w*u0.w;
    float a1s = fv.x*u1.x + fv.y*u1.y + fv.z*u1.z + fv.w*u1.w;
    float a2s = fv.x*u2.x + fv.y*u2.y + fv.z*u2.z + fv.w*u2.w;

    #pragma unroll
    for (int o = 16; o > 0; o >>= 1) {
        a0s += __shfl_xor_sync(FULL, a0s, o);
        a1s += __shfl_xor_sync(FULL, a1s, o);
        a2s += __shfl_xor_sync(FULL, a2s, o);
    }
    __shared__ float s[8][3];
    if (lane == 0) { s[warp][0] = a0s; s[warp][1] = a1s; s[warp][2] = a2s; }
    __syncthreads();
    if (tid == 0) {
        float l0 = __ldg(&cb[0]), l1 = __ldg(&cb[1]), l2 = __ldg(&cb[2]);
        #pragma unroll
        for (int w = 0; w < 8; w++) { l0 += s[w][0]; l1 += s[w][1]; l2 += s[w][2]; }
        float m  = fmaxf(l0, fmaxf(l1, l2));
        float e0 = expf(l0 - m), e1 = expf(l1 - m), e2 = expf(l2 - m);
        float inv = 1.0f / (e0 + e1 + e2);
        out[b * 3 + 0] = e0 * inv;
        out[b * 3 + 1] = e1 * inv;
        out[b * 3 + 2] = e2 * inv;
        g_cnt[b * 32] = 0;                    // reset for the next replay
    }
}

extern "C" void kernel_launch(void* const* d_in, const int* in_sizes, int n_in,
                              void* d_out, int out_size)
{
    // metadata order: input, conv1_w, conv1_b, conv2_w, conv2_b, conv3_w,
    // conv3_b, gcn1_w, gcn1_b, gcn2_w, gcn2_b, cls_w, cls_b  (gcn* are dead)
    const float* x   = (const float*)d_in[0];
    const float* w1  = (const float*)d_in[1];
    const float* b1  = (const float*)d_in[2];
    const float* w2  = (const float*)d_in[3];
    const float* b2  = (const float*)d_in[4];
    const float* w3  = (const float*)d_in[5];
    const float* b3  = (const float*)d_in[6];
    const float* cw  = (const float*)d_in[11];
    const float* cb  = (const float*)d_in[12];
    float* out = (float*)d_out;

    // Single kernel: 8192 producer blocks; the last block of each batch
    // (release/acquire ticket, no L1-flushing fence) computes that batch's
    // classifier head + softmax inline.
    conv_chain_kernel<<<8192, 256>>>(x, w1, b1, w2, b2, w3, b3, cw, cb, out);
}

// round 17
// speedup vs baseline: 1.0815x; 1.0815x over previous
#include <cuda_runtime.h>

#define FULL 0xFFFFFFFFu

// feat[b][n] scratch (64*1024 floats). __device__ global = allowed scratch.
__device__ float g_feat[64 * 1024];

// 6 blocks/SM min -> ptxas caps regs at 42 -> 48 warps/SM (75% occ).
__global__ __launch_bounds__(256, 6) void conv_chain_kernel(
    const float* __restrict__ x,
    const float* __restrict__ w1, const float* __restrict__ b1,
    const float* __restrict__ w2, const float* __restrict__ b2,
    const float* __restrict__ w3, const float* __restrict__ b3)
{
    // 8 warps per block, one row (b,n) per warp.
    __shared__ float sm[8][152];   // conv1 output for the 150->30 pool gather

    const int warp = threadIdx.x >> 5;
    const int lane = threadIdx.x & 31;
    const int row  = blockIdx.x * 8 + warp;   // row in [0, 65536)

    const float4* X4 = reinterpret_cast<const float4*>(x + (size_t)row * 1200);
    float* S = sm[warp];

    // ---- conv1: K=10, stride=8, pad=1, out length 150, relu.
    // Output j = 32*it + lane, window x[8j-1 .. 8j+8].
    // Depth-2 software pipeline: only 4 float4s live at a time (low regs ->
    // high occupancy), while keeping 4 LDG.128s in flight per lane.
    float4 a0, a1;
    {
        int jj = lane;                        // it=0: j = lane < 150 always
        a0 = X4[2 * jj];
        a1 = X4[2 * jj + 1];
    }

    float W1[10];
    #pragma unroll
    for (int k = 0; k < 10; k++) W1[k] = __ldg(&w1[k]);
    const float B1 = __ldg(b1);

    float carry = 0.0f;                       // x[8j-1] carry (x[-1] = pad)
    #pragma unroll
    for (int it = 0; it < 5; it++) {
        // prefetch next iteration's window
        float4 n0, n1;
        if (it < 4) {
            int j  = (it + 1) * 32 + lane;
            int jj = j < 150 ? j : 149;       // clamp (it==4 lanes 22..31 idle)
            n0 = X4[2 * jj];
            n1 = X4[2 * jj + 1];
        }

        // x[8j-1] = previous lane's a1.w
        float xm1 = __shfl_up_sync(FULL, a1.w, 1);
        if (lane == 0) xm1 = carry;
        carry = __shfl_sync(FULL, a1.w, 31);

        // x[8j+8] = next lane's a0.x; lane 31 takes next iter's lane-0 a0.x
        float nxt = (it < 4) ? __shfl_sync(FULL, n0.x, 0) : 0.0f;
        float a2  = __shfl_down_sync(FULL, a0.x, 1);
        if (lane == 31) a2 = nxt;
        int j = it * 32 + lane;
        if (j == 149) a2 = 0.0f;              // right pad

        float v = B1;
        v = fmaf(W1[0], xm1,  v);
        v = fmaf(W1[1], a0.x, v);
        v = fmaf(W1[2], a0.y, v);
        v = fmaf(W1[3], a0.z, v);
        v = fmaf(W1[4], a0.w, v);
        v = fmaf(W1[5], a1.x, v);
        v = fmaf(W1[6], a1.y, v);
        v = fmaf(W1[7], a1.z, v);
        v = fmaf(W1[8], a1.w, v);
        v = fmaf(W1[9], a2,   v);
        if (j < 150) S[j] = fmaxf(v, 0.0f);   // write y1 straight to smem

        a0 = n0; a1 = n1;
    }
    __syncwarp();

    // ---- maxpool k=5 s=5 (150 -> 30); relu no-op (inputs >= 0)
    float p = 0.0f;
    if (lane < 30) {
        p = S[5 * lane];
        #pragma unroll
        for (int k = 1; k < 5; k++) p = fmaxf(p, S[5 * lane + k]);
    }

    // ---- conv2: K=3 s=3 (30 -> 10), relu  (lanes 0..9 produce q)
    const float w20 = __ldg(&w2[0]), w21 = __ldg(&w2[1]), w22 = __ldg(&w2[2]);
    const float B2  = __ldg(b2);
    float pa = __shfl_sync(FULL, p, (3 * lane)     & 31);
    float pb = __shfl_sync(FULL, p, (3 * lane + 1) & 31);
    float pc = __shfl_sync(FULL, p, (3 * lane + 2) & 31);
    float q = fmaxf(fmaf(w20, pa, fmaf(w21, pb, fmaf(w22, pc, B2))), 0.0f);

    // ---- maxpool k=3 s=3 pad=1 (10 -> 4); relu no-op  (lanes 0..3)
    float qm = __shfl_sync(FULL, q, (3 * lane - 1) & 31);
    float q0 = __shfl_sync(FULL, q, (3 * lane)     & 31);
    float qp = __shfl_sync(FULL, q, (3 * lane + 1) & 31);
    float r;
    if (lane == 0)      r = fmaxf(q0, qp);        // window {-1(pad),0,1}
    else if (lane == 3) r = fmaxf(qm, q0);        // window {8,9,10(pad)}
    else                r = fmaxf(fmaxf(qm, q0), qp);

    // ---- conv3: K=4 s=1 (4 -> 1), relu -> feat
    float r0 = __shfl_sync(FULL, r, 0);
    float r1 = __shfl_sync(FULL, r, 1);
    float r2 = __shfl_sync(FULL, r, 2);
    float r3 = __shfl_sync(FULL, r, 3);
    if (lane == 0) {
        float f = __ldg(b3);
        f = fmaf(__ldg(&w3[0]), r0, f);
        f = fmaf(__ldg(&w3[1]), r1, f);
        f = fmaf(__ldg(&w3[2]), r2, f);
        f = fmaf(__ldg(&w3[3]), r3, f);
        g_feat[row] = fmaxf(f, 0.0f);
    }

#if __CUDA_ARCH__ >= 900
    // Allow the PDL-dependent head kernel to begin its prologue.
    cudaTriggerProgrammaticLaunchCompletion();
#endif
}

// logits = feat @ cls_w.T + cls_b ; softmax over 3 classes. One block per batch.
// Launched with programmatic stream serialization: starts during conv tail,
// loads cls_w (independent), then waits on the grid dependency before feat.
__global__ __launch_bounds__(256) void head_kernel(
    const float* __restrict__ cw,   // [3,1024]
    const float* __restrict__ cb,   // [3]
    float* __restrict__ out)        // [64,3]
{
    const int b = blockIdx.x;
    const int t = threadIdx.x;
    const float4* c0 = reinterpret_cast<const float4*>(cw);
    const float4* c1 = reinterpret_cast<const float4*>(cw + 1024);
    const float4* c2 = reinterpret_cast<const float4*>(cw + 2048);

    // Independent prologue: weight loads overlap the conv kernel's tail.
    float4 w0 = __ldg(&c0[t]);
    float4 w1 = __ldg(&c1[t]);
    float4 w2 = __ldg(&c2[t]);
    float cb0 = __ldg(&cb[0]), cb1 = __ldg(&cb[1]), cb2 = __ldg(&cb[2]);

#if __CUDA_ARCH__ >= 900
    cudaGridDependencySynchronize();   // wait for conv grid (g_feat ready)
#endif

    const float4* f4 = reinterpret_cast<const float4*>(g_feat + b * 1024);
    float4 fv = f4[t];

    float a0 = fv.x * w0.x + fv.y * w0.y + fv.z * w0.z + fv.w * w0.w;
    float a1 = fv.x * w1.x + fv.y * w1.y + fv.z * w1.z + fv.w * w1.w;
    float a2 = fv.x * w2.x + fv.y * w2.y + fv.z * w2.z + fv.w * w2.w;

    #pragma unroll
    for (int o = 16; o > 0; o >>= 1) {
        a0 += __shfl_xor_sync(FULL, a0, o);
        a1 += __shfl_xor_sync(FULL, a1, o);
        a2 += __shfl_xor_sync(FULL, a2, o);
    }
    __shared__ float s[8][3];
    if ((t & 31) == 0) {
        int w = t >> 5;
        s[w][0] = a0; s[w][1] = a1; s[w][2] = a2;
    }
    __syncthreads();
    if (t == 0) {
        float l0 = cb0, l1 = cb1, l2 = cb2;
        #pragma unroll
        for (int w = 0; w < 8; w++) { l0 += s[w][0]; l1 += s[w][1]; l2 += s[w][2]; }
        float m  = fmaxf(l0, fmaxf(l1, l2));
        float e0 = expf(l0 - m), e1 = expf(l1 - m), e2 = expf(l2 - m);
        float inv = 1.0f / (e0 + e1 + e2);
        out[b * 3 + 0] = e0 * inv;
        out[b * 3 + 1] = e1 * inv;
        out[b * 3 + 2] = e2 * inv;
    }
}

extern "C" void kernel_launch(void* const* d_in, const int* in_sizes, int n_in,
                              void* d_out, int out_size)
{
    // metadata order: input, conv1_w, conv1_b, conv2_w, conv2_b, conv3_w,
    // conv3_b, gcn1_w, gcn1_b, gcn2_w, gcn2_b, cls_w, cls_b  (gcn* are dead)
    const float* x   = (const float*)d_in[0];
    const float* w1  = (const float*)d_in[1];
    const float* b1  = (const float*)d_in[2];
    const float* w2  = (const float*)d_in[3];
    const float* b2  = (const float*)d_in[4];
    const float* w3  = (const float*)d_in[5];
    const float* b3  = (const float*)d_in[6];
    const float* cw  = (const float*)d_in[11];
    const float* cb  = (const float*)d_in[12];
    float* out = (float*)d_out;

    conv_chain_kernel<<<8192, 256>>>(x, w1, b1, w2, b2, w3, b3);

    // Head with programmatic dependent launch: overlaps its launch + weight
    // prologue with the conv tail; correctness guaranteed by
    // cudaGridDependencySynchronize() in the kernel.
    cudaLaunchAttribute attr[1];
    attr[0].id = cudaLaunchAttributeProgrammaticStreamSerialization;
    attr[0].val.programmaticStreamSerializationAllowed = 1;

    cudaLaunchConfig_t cfg = {};
    cfg.gridDim  = dim3(64, 1, 1);
    cfg.blockDim = dim3(256, 1, 1);
    cfg.dynamicSmemBytes = 0;
    cfg.stream = 0;          // legacy default stream (graph capture target)
    cfg.attrs = attr;
    cfg.numAttrs = 1;

    cudaError_t e = cudaLaunchKernelEx(&cfg, head_kernel, cw, cb, (float*)d_out);
    if (e != cudaSuccess) {
        // Fallback: plain launch (still correct, just no overlap).
        head_kernel<<<64, 256>>>(cw, cb, out);
    }
}